// round 5
// baseline (speedup 1.0000x reference)
#include <cuda_runtime.h>

#define REPS 1e-4f

// Scratch (no allocations allowed). Zero-init at load; counters/flags are
// reset inside the kernel so graph replays see clean state.
__device__ float    g_M[25 * 32];   // each accumulator on its own 128B line
__device__ unsigned g_cnt;          // phase-1 arrival counter
__device__ unsigned g_flag;         // H-ready flag
__device__ unsigned g_cnt2;         // phase-2 finish counter
__device__ float    g_H[5 * 2048];  // H = A5 @ W2

// ---------------------------------------------------------------------------
// Persistent fused kernel. Grid = 4 * numSMs (1D), 256 threads, 4 blocks/SM
// guaranteed resident by __launch_bounds__(256,4) (regs capped at 64, smem
// ~1.6KB). Phases:
//   1) M = W1^T X W1 banded reduction (column-major accumulation)
//   2) last-arriving block: 5x5 Jacobi eigensolve + H = A5@W2, set flag
//   3) all blocks: spin (1 spinner/block), then write z = W2^T H + EPS*I
// ---------------------------------------------------------------------------
__global__ __launch_bounds__(256, 4) void k_fused(const float* __restrict__ X,
                                                  const float* __restrict__ W1,
                                                  const float* __restrict__ W2,
                                                  float* __restrict__ out) {
    const int tid  = threadIdx.x;
    const int bid  = blockIdx.x;
    const int nblk = gridDim.x;           // multiple of 4

    // ---------------- Phase 1: banded projection ----------------
    const int cg    = bid & 3;            // column group: 1024 cols
    const int band  = bid >> 2;
    const int nband = nblk >> 2;
    const int j0    = cg * 1024 + tid * 4;
    const int r0    = (int)(((long long)band * 4096) / nband);
    const int r1    = (int)(((long long)(band + 1) * 4096) / nband);
    const int R     = r1 - r0;

    __shared__ float sW1[32 * 5];
    __shared__ float sM[8][25];
    __shared__ float sA5[25];
    __shared__ bool  sLast;
    if (tid < R * 5) sW1[tid] = W1[r0 * 5 + tid];
    __syncthreads();

    float tacc[4][5];
#pragma unroll
    for (int cc = 0; cc < 4; cc++)
#pragma unroll
        for (int a = 0; a < 5; a++) tacc[cc][a] = 0.f;

    const float* Xb = X + (size_t)r0 * 4096 + j0;
    int r = 0;
    for (; r + 4 <= R; r += 4) {
        const float4 x0 = __ldcs(reinterpret_cast<const float4*>(Xb + (size_t)(r + 0) * 4096));
        const float4 x1 = __ldcs(reinterpret_cast<const float4*>(Xb + (size_t)(r + 1) * 4096));
        const float4 x2 = __ldcs(reinterpret_cast<const float4*>(Xb + (size_t)(r + 2) * 4096));
        const float4 x3 = __ldcs(reinterpret_cast<const float4*>(Xb + (size_t)(r + 3) * 4096));
        const float4 xs[4] = {x0, x1, x2, x3};
#pragma unroll
        for (int k = 0; k < 4; k++) {
            const float xv[4] = {xs[k].x, xs[k].y, xs[k].z, xs[k].w};
            float w[5];
#pragma unroll
            for (int a = 0; a < 5; a++) w[a] = sW1[(r + k) * 5 + a];
#pragma unroll
            for (int cc = 0; cc < 4; cc++)
#pragma unroll
                for (int a = 0; a < 5; a++) tacc[cc][a] += xv[cc] * w[a];
        }
    }
    for (; r < R; r++) {
        const float4 x = __ldcs(reinterpret_cast<const float4*>(Xb + (size_t)r * 4096));
        const float xv[4] = {x.x, x.y, x.z, x.w};
        float w[5];
#pragma unroll
        for (int a = 0; a < 5; a++) w[a] = sW1[r * 5 + a];
#pragma unroll
        for (int cc = 0; cc < 4; cc++)
#pragma unroll
            for (int a = 0; a < 5; a++) tacc[cc][a] += xv[cc] * w[a];
    }

    // Fold with W1[j,b] once per thread
    float mp[5][5];
#pragma unroll
    for (int a = 0; a < 5; a++)
#pragma unroll
        for (int b = 0; b < 5; b++) mp[a][b] = 0.f;
#pragma unroll
    for (int cc = 0; cc < 4; cc++) {
        float w1j[5];
#pragma unroll
        for (int b = 0; b < 5; b++) w1j[b] = __ldg(W1 + (j0 + cc) * 5 + b);
#pragma unroll
        for (int a = 0; a < 5; a++)
#pragma unroll
            for (int b = 0; b < 5; b++) mp[a][b] += tacc[cc][a] * w1j[b];
    }

    // Block reduce 25 values -> 25 padded global atomics
    const int lane = tid & 31, warp = tid >> 5;
#pragma unroll
    for (int e = 0; e < 25; e++) {
        float v = mp[e / 5][e % 5];
#pragma unroll
        for (int o = 16; o > 0; o >>= 1) v += __shfl_down_sync(0xffffffffu, v, o);
        if (lane == 0) sM[warp][e] = v;
    }
    __syncthreads();
    if (tid < 25) {
        float v = 0.f;
#pragma unroll
        for (int wq = 0; wq < 8; wq++) v += sM[wq][tid];
        atomicAdd(&g_M[tid * 32], v);
    }
    if (tid == 0) {
        __threadfence();
        sLast = (atomicAdd(&g_cnt, 1u) == (unsigned)nblk - 1u);
    }
    __syncthreads();

    // ---------------- Phase 2 (last block only): Jacobi + H ----------------
    if (sLast) {
        if (tid == 0) {
            float m[5][5], b[5][5], u[5][5];
#pragma unroll
            for (int a = 0; a < 5; a++)
#pragma unroll
                for (int c = 0; c < 5; c++) m[a][c] = __ldcg(&g_M[(a * 5 + c) * 32]);

            float tr = 0.f;
#pragma unroll
            for (int a = 0; a < 5; a++)
#pragma unroll
                for (int c = 0; c < 5; c++) {
                    float s = 0.f;
#pragma unroll
                    for (int k = 0; k < 5; k++) s += m[a][k] * m[c][k];
                    b[a][c] = s;
                    u[a][c] = (a == c) ? 1.f : 0.f;
                    if (a == c) tr += s;
                }
            const float skip_tol = 1e-7f * tr;

#pragma unroll
            for (int sweep = 0; sweep < 5; sweep++) {
#pragma unroll
                for (int p = 0; p < 4; p++) {
#pragma unroll
                    for (int q = p + 1; q < 5; q++) {
                        const float apq = b[p][q];
                        if (fabsf(apq) > skip_tol) {
                            const float tau = (b[q][q] - b[p][p]) / (2.f * apq);
                            const float t   = copysignf(1.f, tau) / (fabsf(tau) + sqrtf(1.f + tau * tau));
                            const float c   = rsqrtf(1.f + t * t);
                            const float s   = t * c;
#pragma unroll
                            for (int k = 0; k < 5; k++) {
                                const float bkp = b[k][p], bkq = b[k][q];
                                b[k][p] = c * bkp - s * bkq;
                                b[k][q] = s * bkp + c * bkq;
                            }
#pragma unroll
                            for (int k = 0; k < 5; k++) {
                                const float bpk = b[p][k], bqk = b[q][k];
                                b[p][k] = c * bpk - s * bqk;
                                b[q][k] = s * bpk + c * bqk;
                                const float ukp = u[k][p], ukq = u[k][q];
                                u[k][p] = c * ukp - s * ukq;
                                u[k][q] = s * ukp + c * ukq;
                            }
                        }
                    }
                }
            }

            float f[5];
#pragma unroll
            for (int d = 0; d < 5; d++) {
                const float lam = fmaxf(b[d][d], 0.f);
                f[d] = fmaxf(sqrtf(lam), REPS) - REPS;
            }
#pragma unroll
            for (int a = 0; a < 5; a++)
#pragma unroll
                for (int c = 0; c < 5; c++) {
                    float s = 0.f;
#pragma unroll
                    for (int d = 0; d < 5; d++) s += u[a][d] * f[d] * u[c][d];
                    sA5[a * 5 + c] = s;
                }

            // Reset phase-1 scratch for the next graph replay
#pragma unroll
            for (int e = 0; e < 25; e++) g_M[e * 32] = 0.f;
            g_cnt = 0u;
        }
        __syncthreads();

        // H[a][j] = sum_b A5[a][b] * W2[b][j]
        float a5l[5][5];
#pragma unroll
        for (int a = 0; a < 5; a++)
#pragma unroll
            for (int c = 0; c < 5; c++) a5l[a][c] = sA5[a * 5 + c];
#pragma unroll
        for (int k = 0; k < 8; k++) {
            const int j = tid + 256 * k;
            float w2j[5];
#pragma unroll
            for (int b2 = 0; b2 < 5; b2++) w2j[b2] = __ldg(W2 + b2 * 2048 + j);
#pragma unroll
            for (int a = 0; a < 5; a++) {
                float s = 0.f;
#pragma unroll
                for (int b2 = 0; b2 < 5; b2++) s += a5l[a][b2] * w2j[b2];
                g_H[a * 2048 + j] = s;
            }
        }
        __syncthreads();
        if (tid == 0) {
            __threadfence();
            atomicExch(&g_flag, 1u);
        }
    }

    // ---------------- Grid sync: wait for H ----------------
    if (tid == 0) {
        while (atomicAdd(&g_flag, 0u) == 0u) __nanosleep(64);
        __threadfence();
    }
    __syncthreads();

    // ---------------- Phase 3: z = W2^T H + EPS*I ----------------
    // Block covers a contiguous row band of one 1024-col half.
    const int jh    = bid & 1;
    const int band2 = bid >> 1;
    const int nb2   = nblk >> 1;
    const int jo    = jh * 1024 + tid * 4;
    const int o0    = (int)(((long long)band2 * 2048) / nb2);
    const int o1    = (int)(((long long)(band2 + 1) * 2048) / nb2);

    float4 h[5];
#pragma unroll
    for (int a = 0; a < 5; a++)
        h[a] = *reinterpret_cast<const float4*>(g_H + a * 2048 + jo);   // ldcg not
                                                                        // needed: L1
                                                                        // has no stale
                                                                        // copy, but be
                                                                        // safe below
#pragma unroll
    for (int a = 0; a < 5; a++) {
        // re-load via L2 to guarantee coherence with producer block
        h[a].x = __ldcg(g_H + a * 2048 + jo + 0);
        h[a].y = __ldcg(g_H + a * 2048 + jo + 1);
        h[a].z = __ldcg(g_H + a * 2048 + jo + 2);
        h[a].w = __ldcg(g_H + a * 2048 + jo + 3);
    }

    int i = o0;
    float w[5];
#pragma unroll
    for (int a = 0; a < 5; a++) w[a] = __ldg(W2 + a * 2048 + i);
    while (true) {
        const int inx = i + 1;
        const bool more = (inx < o1);
        float wn[5];
        if (more) {
#pragma unroll
            for (int a = 0; a < 5; a++) wn[a] = __ldg(W2 + a * 2048 + inx);
        }
        float4 v;
        v.x = w[0] * h[0].x; v.y = w[0] * h[0].y;
        v.z = w[0] * h[0].z; v.w = w[0] * h[0].w;
#pragma unroll
        for (int a = 1; a < 5; a++) {
            v.x += w[a] * h[a].x; v.y += w[a] * h[a].y;
            v.z += w[a] * h[a].z; v.w += w[a] * h[a].w;
        }
        const int d = i - jo;
        if ((unsigned)d < 4u) {
            if (d == 0) v.x += REPS;
            else if (d == 1) v.y += REPS;
            else if (d == 2) v.z += REPS;
            else v.w += REPS;
        }
        *reinterpret_cast<float4*>(out + (size_t)i * 2048 + jo) = v;
        if (!more) break;
        i = inx;
#pragma unroll
        for (int a = 0; a < 5; a++) w[a] = wn[a];
    }

    // ---------------- Epilogue: last finisher resets flags ----------------
    __syncthreads();
    if (tid == 0) {
        __threadfence();
        if (atomicAdd(&g_cnt2, 1u) == (unsigned)nblk - 1u) {
            g_flag = 0u;
            g_cnt2 = 0u;
        }
    }
}

// ---------------------------------------------------------------------------
extern "C" void kernel_launch(void* const* d_in, const int* in_sizes, int n_in,
                              void* d_out, int out_size) {
    const float* X  = (const float*)d_in[0];   // (1, 4096, 4096) f32
    const float* W1 = (const float*)d_in[1];   // (4096, 5) f32
    const float* W2 = (const float*)d_in[2];   // (5, 2048) f32
    float* out = (float*)d_out;                // (2048, 2048) f32

    int dev = 0, sms = 148;
    cudaGetDevice(&dev);
    cudaDeviceGetAttribute(&sms, cudaDevAttrMultiProcessorCount, dev);
    const int nblk = 4 * sms;                  // 4 resident blocks per SM

    k_fused<<<nblk, 256>>>(X, W1, W2, out);
}

// round 6
// speedup vs baseline: 1.0583x; 1.0583x over previous
#include <cuda_runtime.h>

#define REPS 1e-4f
#define GYP 148
#define NBLK_PROJ (4 * GYP)

// Scratch (no allocations allowed). Zero-init at load; last k_proj block
// resets g_M/g_cnt after consuming, so graph replays see clean state.
__device__ float    g_M[25 * 32];  // each accumulator on its own 128B line
__device__ unsigned g_cnt;
__device__ float    g_H[5 * 2048]; // H = A5 @ W2, produced by last proj block

// ---- packed f32x2 helpers --------------------------------------------------
__device__ __forceinline__ unsigned long long ffma2(unsigned long long a,
                                                    unsigned long long b,
                                                    unsigned long long c) {
    unsigned long long d;
    asm("fma.rn.f32x2 %0, %1, %2, %3;" : "=l"(d) : "l"(a), "l"(b), "l"(c));
    return d;
}
__device__ __forceinline__ float2 unpack2(unsigned long long v) {
    float2 r;
    asm("mov.b64 {%0, %1}, %2;" : "=f"(r.x), "=f"(r.y) : "l"(v));
    return r;
}
__device__ __forceinline__ unsigned long long pack_dup(float v) {
    unsigned long long d;
    asm("mov.b64 %0, {%1, %1};" : "=l"(d) : "f"(v));
    return d;
}

// ---------------------------------------------------------------------------
// K1: t[j][a] = sum_i W1[i,a]*X[i,j]; fold M[a][b] += t[j][a]*W1[j,b] once.
// Block: 256 thr, 1024-col tile (4 cols/thread as 2 f32x2 lanes), contiguous
// row band with W1 staged in smem as DUPLICATED PAIRS (ld.shared.b64).
// Inner row: 5 LDS.64 + 10 fma.rn.f32x2, rows unrolled x4, loads batched.
// Last block: thread 0 runs 5x5 Jacobi, then 256 threads emit H = A5@W2.
// ---------------------------------------------------------------------------
__global__ __launch_bounds__(256, 4) void k_proj(const float* __restrict__ X,
                                                 const float* __restrict__ W1,
                                                 const float* __restrict__ W2) {
    const int tid = threadIdx.x;
    const int j0  = blockIdx.x * 1024 + tid * 4;
    const int r0  = (blockIdx.y * 4096) / GYP;
    const int r1  = ((blockIdx.y + 1) * 4096) / GYP;
    const int R   = r1 - r0;                      // 27 or 28

    __shared__ __align__(8) unsigned long long sW1d[28 * 5]; // (w,w) pairs
    __shared__ float sM[8][25];
    __shared__ float sA5[25];
    __shared__ bool  sLast;
    if (tid < R * 5) sW1d[tid] = pack_dup(W1[r0 * 5 + tid]);
    __syncthreads();

    unsigned long long tacc[2][5];   // [pair(lo cols 0,1 / hi cols 2,3)][a]
#pragma unroll
    for (int p = 0; p < 2; p++)
#pragma unroll
        for (int a = 0; a < 5; a++) tacc[p][a] = 0ull;

    const float* Xb = X + (size_t)r0 * 4096 + j0;
    int r = 0;
    for (; r + 4 <= R; r += 4) {
        ulonglong2 xs[4];
#pragma unroll
        for (int k = 0; k < 4; k++)
            xs[k] = __ldcs(reinterpret_cast<const ulonglong2*>(Xb + (size_t)(r + k) * 4096));
#pragma unroll
        for (int k = 0; k < 4; k++) {
            unsigned long long wd[5];
#pragma unroll
            for (int a = 0; a < 5; a++) wd[a] = sW1d[(r + k) * 5 + a];
#pragma unroll
            for (int a = 0; a < 5; a++) {
                tacc[0][a] = ffma2(xs[k].x, wd[a], tacc[0][a]);
                tacc[1][a] = ffma2(xs[k].y, wd[a], tacc[1][a]);
            }
        }
    }
    for (; r < R; r++) {
        const ulonglong2 x = __ldcs(reinterpret_cast<const ulonglong2*>(Xb + (size_t)r * 4096));
        unsigned long long wd[5];
#pragma unroll
        for (int a = 0; a < 5; a++) wd[a] = sW1d[r * 5 + a];
#pragma unroll
        for (int a = 0; a < 5; a++) {
            tacc[0][a] = ffma2(x.x, wd[a], tacc[0][a]);
            tacc[1][a] = ffma2(x.y, wd[a], tacc[1][a]);
        }
    }

    // Unpack and fold with W1[j,b] once per thread
    float tc[4][5];
#pragma unroll
    for (int a = 0; a < 5; a++) {
        const float2 lo = unpack2(tacc[0][a]);
        const float2 hi = unpack2(tacc[1][a]);
        tc[0][a] = lo.x; tc[1][a] = lo.y; tc[2][a] = hi.x; tc[3][a] = hi.y;
    }
    float mp[5][5];
#pragma unroll
    for (int a = 0; a < 5; a++)
#pragma unroll
        for (int b = 0; b < 5; b++) mp[a][b] = 0.f;
#pragma unroll
    for (int cc = 0; cc < 4; cc++) {
        float w1j[5];
#pragma unroll
        for (int b = 0; b < 5; b++) w1j[b] = __ldg(W1 + (j0 + cc) * 5 + b);
#pragma unroll
        for (int a = 0; a < 5; a++)
#pragma unroll
            for (int b = 0; b < 5; b++) mp[a][b] += tc[cc][a] * w1j[b];
    }

    // Block reduce 25 values -> 25 padded global atomics
    const int lane = tid & 31, warp = tid >> 5;
#pragma unroll
    for (int e = 0; e < 25; e++) {
        float v = mp[e / 5][e % 5];
#pragma unroll
        for (int o = 16; o > 0; o >>= 1) v += __shfl_down_sync(0xffffffffu, v, o);
        if (lane == 0) sM[warp][e] = v;
    }
    __syncthreads();
    if (tid < 25) {
        float v = 0.f;
#pragma unroll
        for (int wq = 0; wq < 8; wq++) v += sM[wq][tid];
        atomicAdd(&g_M[tid * 32], v);
    }
    if (tid == 0) {
        __threadfence();
        sLast = (atomicAdd(&g_cnt, 1u) == (unsigned)NBLK_PROJ - 1u);
    }
    __syncthreads();
    if (!sLast) return;

    // ---- Last block. Thread 0: B = M*M^T ; Jacobi ; A5 -> shared ----
    if (tid == 0) {
        float m[5][5], b[5][5], u[5][5];
#pragma unroll
        for (int a = 0; a < 5; a++)
#pragma unroll
            for (int c = 0; c < 5; c++) m[a][c] = __ldcg(&g_M[(a * 5 + c) * 32]);

        float tr = 0.f;
#pragma unroll
        for (int a = 0; a < 5; a++)
#pragma unroll
            for (int c = 0; c < 5; c++) {
                float s = 0.f;
#pragma unroll
                for (int k = 0; k < 5; k++) s += m[a][k] * m[c][k];
                b[a][c] = s;
                u[a][c] = (a == c) ? 1.f : 0.f;
                if (a == c) tr += s;
            }
        const float skip_tol = 1e-7f * tr;

#pragma unroll
        for (int sweep = 0; sweep < 5; sweep++) {
#pragma unroll
            for (int p = 0; p < 4; p++) {
#pragma unroll
                for (int q = p + 1; q < 5; q++) {
                    const float apq = b[p][q];
                    if (fabsf(apq) > skip_tol) {
                        const float tau = (b[q][q] - b[p][p]) / (2.f * apq);
                        const float t   = copysignf(1.f, tau) / (fabsf(tau) + sqrtf(1.f + tau * tau));
                        const float c   = rsqrtf(1.f + t * t);
                        const float s   = t * c;
#pragma unroll
                        for (int k = 0; k < 5; k++) {
                            const float bkp = b[k][p], bkq = b[k][q];
                            b[k][p] = c * bkp - s * bkq;
                            b[k][q] = s * bkp + c * bkq;
                        }
#pragma unroll
                        for (int k = 0; k < 5; k++) {
                            const float bpk = b[p][k], bqk = b[q][k];
                            b[p][k] = c * bpk - s * bqk;
                            b[q][k] = s * bpk + c * bqk;
                            const float ukp = u[k][p], ukq = u[k][q];
                            u[k][p] = c * ukp - s * ukq;
                            u[k][q] = s * ukp + c * ukq;
                        }
                    }
                }
            }
        }

        float f[5];
#pragma unroll
        for (int d = 0; d < 5; d++) {
            const float lam = fmaxf(b[d][d], 0.f);
            f[d] = fmaxf(sqrtf(lam), REPS) - REPS;
        }
#pragma unroll
        for (int a = 0; a < 5; a++)
#pragma unroll
            for (int c = 0; c < 5; c++) {
                float s = 0.f;
#pragma unroll
                for (int d = 0; d < 5; d++) s += u[a][d] * f[d] * u[c][d];
                sA5[a * 5 + c] = s;
            }

        // Reset scratch for the next graph replay
#pragma unroll
        for (int e = 0; e < 25; e++) g_M[e * 32] = 0.f;
        g_cnt = 0u;
    }
    __syncthreads();

    // ---- All 256 threads: H[a][j] = sum_b A5[a][b] * W2[b][j] -> g_H ----
    float a5[5][5];
#pragma unroll
    for (int a = 0; a < 5; a++)
#pragma unroll
        for (int c = 0; c < 5; c++) a5[a][c] = sA5[a * 5 + c];
#pragma unroll
    for (int k = 0; k < 8; k++) {
        const int j = tid + 256 * k;
        float w2j[5];
#pragma unroll
        for (int b2 = 0; b2 < 5; b2++) w2j[b2] = __ldg(W2 + b2 * 2048 + j);
#pragma unroll
        for (int a = 0; a < 5; a++) {
            float s = 0.f;
#pragma unroll
            for (int b2 = 0; b2 < 5; b2++) s += a5[a][b2] * w2j[b2];
            g_H[a * 2048 + j] = s;
        }
    }
}

// ---------------------------------------------------------------------------
// K2: z[i][j] = sum_a W2[a,i] * H[a,j] + EPS*(i==j)
// Block: 256 thr, 1024-col half, contiguous row band (grid (2,296), 4/SM,
// one wave). W2 band slice staged in smem as duplicated pairs ONCE; inner
// row loop is 5 LDS.64 + 10 fma.rn.f32x2 + STG.128 — zero LDG.
// ---------------------------------------------------------------------------
__global__ __launch_bounds__(256, 4) void k_out(const float* __restrict__ W2,
                                                float* __restrict__ out) {
    const int tid = threadIdx.x;
    const int jo  = blockIdx.x * 1024 + tid * 4;
    const int o0  = (blockIdx.y * 2048) / 296;
    const int o1  = ((blockIdx.y + 1) * 2048) / 296;
    const int RR  = o1 - o0;                      // 6 or 7

    __shared__ __align__(8) unsigned long long sW2d[8 * 5];  // (w,w) per row,a
    if (tid < RR * 5) {
        const int rr = tid / 5, a = tid % 5;
        sW2d[tid] = pack_dup(__ldg(W2 + a * 2048 + o0 + rr));
    }

    ulonglong2 h[5];
#pragma unroll
    for (int a = 0; a < 5; a++)
        h[a] = *reinterpret_cast<const ulonglong2*>(g_H + a * 2048 + jo);
    __syncthreads();

    for (int rr = 0; rr < RR; rr++) {
        const int i = o0 + rr;
        unsigned long long wd[5];
#pragma unroll
        for (int a = 0; a < 5; a++) wd[a] = sW2d[rr * 5 + a];

        unsigned long long vlo = 0ull, vhi = 0ull;
#pragma unroll
        for (int a = 0; a < 5; a++) {
            vlo = ffma2(wd[a], h[a].x, vlo);
            vhi = ffma2(wd[a], h[a].y, vhi);
        }
        const float2 flo = unpack2(vlo);
        const float2 fhi = unpack2(vhi);
        float4 v;
        v.x = flo.x; v.y = flo.y; v.z = fhi.x; v.w = fhi.y;

        const int d = i - jo;
        if ((unsigned)d < 4u) {
            if (d == 0) v.x += REPS;
            else if (d == 1) v.y += REPS;
            else if (d == 2) v.z += REPS;
            else v.w += REPS;
        }
        *reinterpret_cast<float4*>(out + (size_t)i * 2048 + jo) = v;
    }
}

// ---------------------------------------------------------------------------
extern "C" void kernel_launch(void* const* d_in, const int* in_sizes, int n_in,
                              void* d_out, int out_size) {
    const float* X  = (const float*)d_in[0];   // (1, 4096, 4096) f32
    const float* W1 = (const float*)d_in[1];   // (4096, 5) f32
    const float* W2 = (const float*)d_in[2];   // (5, 2048) f32
    float* out = (float*)d_out;                // (2048, 2048) f32

    k_proj<<<dim3(4, GYP), 256>>>(X, W1, W2);
    k_out <<<dim3(2, 296), 256>>>(W2, out);
}

// round 7
// speedup vs baseline: 1.1083x; 1.0472x over previous
#include <cuda_runtime.h>

#define REPS 1e-4f
#define GYP 148
#define NBLK_PROJ (4 * GYP)

// Scratch (no allocations allowed). Zero-init at load; last k_proj block
// resets g_M/g_cnt after consuming, so graph replays see clean state.
__device__ float    g_M[25 * 32];  // each accumulator on its own 128B line
__device__ unsigned g_cnt;
__device__ float    g_H[5 * 2048]; // H = A5 @ W2, produced by last proj block

// ---------------------------------------------------------------------------
// K1: t[j][a] = sum_i W1[i,a]*X[i,j]; fold M[a][b] += t[j][a]*W1[j,b] once.
// Block: 256 thr, 1024-col x-tile (4 cols/thread), contiguous row band
// [r0,r1) with W1 rows staged in shared. X loaded with DEFAULT cache policy
// (evict-normal): X (64MB) + out (16MB) fit in L2 (~126MB), so across graph
// replays X stays L2-resident (~12TB/s) instead of re-streaming from DRAM.
// Inner loop unrolled x4 with front-batched LDG.128.
// Last block: thread 0 runs 5x5 Jacobi; 256 threads emit H = A5@W2.
// ---------------------------------------------------------------------------
__global__ __launch_bounds__(256, 4) void k_proj(const float* __restrict__ X,
                                                 const float* __restrict__ W1,
                                                 const float* __restrict__ W2) {
    const int tid = threadIdx.x;
    const int j0  = blockIdx.x * 1024 + tid * 4;
    const int r0  = (blockIdx.y * 4096) / GYP;
    const int r1  = ((blockIdx.y + 1) * 4096) / GYP;
    const int R   = r1 - r0;                      // 27 or 28

    __shared__ float sW1[28 * 5];
    __shared__ float sM[8][25];
    __shared__ float sA5[25];
    __shared__ bool  sLast;
    if (tid < R * 5) sW1[tid] = W1[r0 * 5 + tid];
    __syncthreads();

    float tacc[4][5];
#pragma unroll
    for (int cc = 0; cc < 4; cc++)
#pragma unroll
        for (int a = 0; a < 5; a++) tacc[cc][a] = 0.f;

    const float* Xb = X + (size_t)r0 * 4096 + j0;
    int r = 0;
    for (; r + 4 <= R; r += 4) {
        const float4 x0 = *reinterpret_cast<const float4*>(Xb + (size_t)(r + 0) * 4096);
        const float4 x1 = *reinterpret_cast<const float4*>(Xb + (size_t)(r + 1) * 4096);
        const float4 x2 = *reinterpret_cast<const float4*>(Xb + (size_t)(r + 2) * 4096);
        const float4 x3 = *reinterpret_cast<const float4*>(Xb + (size_t)(r + 3) * 4096);
        const float4 xs[4] = {x0, x1, x2, x3};
#pragma unroll
        for (int k = 0; k < 4; k++) {
            const float xv[4] = {xs[k].x, xs[k].y, xs[k].z, xs[k].w};
            float w[5];
#pragma unroll
            for (int a = 0; a < 5; a++) w[a] = sW1[(r + k) * 5 + a];
#pragma unroll
            for (int cc = 0; cc < 4; cc++)
#pragma unroll
                for (int a = 0; a < 5; a++) tacc[cc][a] += xv[cc] * w[a];
        }
    }
    for (; r < R; r++) {
        const float4 x = *reinterpret_cast<const float4*>(Xb + (size_t)r * 4096);
        const float xv[4] = {x.x, x.y, x.z, x.w};
        float w[5];
#pragma unroll
        for (int a = 0; a < 5; a++) w[a] = sW1[r * 5 + a];
#pragma unroll
        for (int cc = 0; cc < 4; cc++)
#pragma unroll
            for (int a = 0; a < 5; a++) tacc[cc][a] += xv[cc] * w[a];
    }

    // Fold with W1[j,b] once per thread
    float mp[5][5];
#pragma unroll
    for (int a = 0; a < 5; a++)
#pragma unroll
        for (int b = 0; b < 5; b++) mp[a][b] = 0.f;
#pragma unroll
    for (int cc = 0; cc < 4; cc++) {
        float w1j[5];
#pragma unroll
        for (int b = 0; b < 5; b++) w1j[b] = __ldg(W1 + (j0 + cc) * 5 + b);
#pragma unroll
        for (int a = 0; a < 5; a++)
#pragma unroll
            for (int b = 0; b < 5; b++) mp[a][b] += tacc[cc][a] * w1j[b];
    }

    // Block reduce 25 values -> 25 padded global atomics
    const int lane = tid & 31, warp = tid >> 5;
#pragma unroll
    for (int e = 0; e < 25; e++) {
        float v = mp[e / 5][e % 5];
#pragma unroll
        for (int o = 16; o > 0; o >>= 1) v += __shfl_down_sync(0xffffffffu, v, o);
        if (lane == 0) sM[warp][e] = v;
    }
    __syncthreads();
    if (tid < 25) {
        float v = 0.f;
#pragma unroll
        for (int wq = 0; wq < 8; wq++) v += sM[wq][tid];
        atomicAdd(&g_M[tid * 32], v);
    }
    if (tid == 0) {
        __threadfence();
        sLast = (atomicAdd(&g_cnt, 1u) == (unsigned)NBLK_PROJ - 1u);
    }
    __syncthreads();
    if (!sLast) return;

    // ---- Last block. Thread 0: B = M*M^T ; Jacobi ; A5 -> shared ----
    if (tid == 0) {
        float m[5][5], b[5][5], u[5][5];
#pragma unroll
        for (int a = 0; a < 5; a++)
#pragma unroll
            for (int c = 0; c < 5; c++) m[a][c] = __ldcg(&g_M[(a * 5 + c) * 32]);

        float tr = 0.f;
#pragma unroll
        for (int a = 0; a < 5; a++)
#pragma unroll
            for (int c = 0; c < 5; c++) {
                float s = 0.f;
#pragma unroll
                for (int k = 0; k < 5; k++) s += m[a][k] * m[c][k];
                b[a][c] = s;
                u[a][c] = (a == c) ? 1.f : 0.f;
                if (a == c) tr += s;
            }
        const float skip_tol = 1e-7f * tr;

#pragma unroll
        for (int sweep = 0; sweep < 5; sweep++) {
#pragma unroll
            for (int p = 0; p < 4; p++) {
#pragma unroll
                for (int q = p + 1; q < 5; q++) {
                    const float apq = b[p][q];
                    if (fabsf(apq) > skip_tol) {
                        const float tau = (b[q][q] - b[p][p]) / (2.f * apq);
                        const float t   = copysignf(1.f, tau) / (fabsf(tau) + sqrtf(1.f + tau * tau));
                        const float c   = rsqrtf(1.f + t * t);
                        const float s   = t * c;
#pragma unroll
                        for (int k = 0; k < 5; k++) {
                            const float bkp = b[k][p], bkq = b[k][q];
                            b[k][p] = c * bkp - s * bkq;
                            b[k][q] = s * bkp + c * bkq;
                        }
#pragma unroll
                        for (int k = 0; k < 5; k++) {
                            const float bpk = b[p][k], bqk = b[q][k];
                            b[p][k] = c * bpk - s * bqk;
                            b[q][k] = s * bpk + c * bqk;
                            const float ukp = u[k][p], ukq = u[k][q];
                            u[k][p] = c * ukp - s * ukq;
                            u[k][q] = s * ukp + c * ukq;
                        }
                    }
                }
            }
        }

        float f[5];
#pragma unroll
        for (int d = 0; d < 5; d++) {
            const float lam = fmaxf(b[d][d], 0.f);
            f[d] = fmaxf(sqrtf(lam), REPS) - REPS;
        }
#pragma unroll
        for (int a = 0; a < 5; a++)
#pragma unroll
            for (int c = 0; c < 5; c++) {
                float s = 0.f;
#pragma unroll
                for (int d = 0; d < 5; d++) s += u[a][d] * f[d] * u[c][d];
                sA5[a * 5 + c] = s;
            }

        // Reset scratch for the next graph replay
#pragma unroll
        for (int e = 0; e < 25; e++) g_M[e * 32] = 0.f;
        g_cnt = 0u;
    }
    __syncthreads();

    // ---- All 256 threads: H[a][j] = sum_b A5[a][b] * W2[b][j] -> g_H ----
    float a5[5][5];
#pragma unroll
    for (int a = 0; a < 5; a++)
#pragma unroll
        for (int c = 0; c < 5; c++) a5[a][c] = sA5[a * 5 + c];
#pragma unroll
    for (int k = 0; k < 8; k++) {
        const int j = tid + 256 * k;
        float w2j[5];
#pragma unroll
        for (int b2 = 0; b2 < 5; b2++) w2j[b2] = __ldg(W2 + b2 * 2048 + j);
#pragma unroll
        for (int a = 0; a < 5; a++) {
            float s = 0.f;
#pragma unroll
            for (int b2 = 0; b2 < 5; b2++) s += a5[a][b2] * w2j[b2];
            g_H[a * 2048 + j] = s;
        }
    }
}

// ---------------------------------------------------------------------------
// K2: z[i][j] = sum_a W2[a,i] * H[a,j] + EPS*(i==j)
// Prologue: 5 coalesced float4 loads of H (L2-resident). Row loop prefetch-
// pipelined; stores perfectly coalesced float4.
// ---------------------------------------------------------------------------
__global__ __launch_bounds__(256, 5) void k_out(const float* __restrict__ W2,
                                                float* __restrict__ out) {
    const int tid = threadIdx.x;
    const int j0  = blockIdx.x * 1024 + tid * 4;

    float4 h[5];
#pragma unroll
    for (int a = 0; a < 5; a++)
        h[a] = *reinterpret_cast<const float4*>(g_H + a * 2048 + j0);

    int i = blockIdx.y;
    float w[5];
#pragma unroll
    for (int a = 0; a < 5; a++) w[a] = __ldg(W2 + a * 2048 + i);

    while (true) {
        const int inx = i + 296;
        const bool more = (inx < 2048);
        float wn[5];
        if (more) {
#pragma unroll
            for (int a = 0; a < 5; a++) wn[a] = __ldg(W2 + a * 2048 + inx);
        }
        float4 v;
        v.x = w[0] * h[0].x; v.y = w[0] * h[0].y;
        v.z = w[0] * h[0].z; v.w = w[0] * h[0].w;
#pragma unroll
        for (int a = 1; a < 5; a++) {
            v.x += w[a] * h[a].x; v.y += w[a] * h[a].y;
            v.z += w[a] * h[a].z; v.w += w[a] * h[a].w;
        }
        const int d = i - j0;
        if ((unsigned)d < 4u) {
            if (d == 0) v.x += REPS;
            else if (d == 1) v.y += REPS;
            else if (d == 2) v.z += REPS;
            else v.w += REPS;
        }
        *reinterpret_cast<float4*>(out + (size_t)i * 2048 + j0) = v;
        if (!more) break;
        i = inx;
#pragma unroll
        for (int a = 0; a < 5; a++) w[a] = wn[a];
    }
}

// ---------------------------------------------------------------------------
extern "C" void kernel_launch(void* const* d_in, const int* in_sizes, int n_in,
                              void* d_out, int out_size) {
    const float* X  = (const float*)d_in[0];   // (1, 4096, 4096) f32
    const float* W1 = (const float*)d_in[1];   // (4096, 5) f32
    const float* W2 = (const float*)d_in[2];   // (5, 2048) f32
    float* out = (float*)d_out;                // (2048, 2048) f32

    k_proj<<<dim3(4, GYP), 256>>>(X, W1, W2);
    k_out <<<dim3(2, 296), 256>>>(W2, out);
}